// round 1
// baseline (speedup 1.0000x reference)
#include <cuda_runtime.h>
#include <cuda_bf16.h>
#include <cstdint>

// Problem constants (validated against in_sizes at launch)
#define IN_F   256
#define OUT_F  128
#define NNODES 100000

// Scratch: support = X @ W   [NNODES, OUT_F] fp32  (51.2 MB)
__device__ float g_support[(size_t)NNODES * OUT_F];
// CSR row pointers derived from sorted edge_dst
__device__ int   g_row_start[NNODES + 1];

// ---------------------------------------------------------------------------
// Kernel 1: SGEMM  support[M,128] = X[M,256] @ W[256,128]
// 128x128 block tile, 8x8 per-thread tile, BK=8, 256 threads.
// ---------------------------------------------------------------------------
#define BM 128
#define BN 128
#define BK 8
#define TM 8
#define TN 8

__global__ __launch_bounds__(256, 2)
void sgemm_xw_kernel(const float* __restrict__ A,   // [M, 256]
                     const float* __restrict__ B,   // [256, 128]
                     int M)
{
    __shared__ float As[BK][BM];   // A stored transposed: As[k][m]
    __shared__ float Bs[BK][BN];

    const int tid  = threadIdx.x;
    const int row0 = blockIdx.x * BM;
    const int tx   = tid & 15;     // 0..15  -> col group
    const int ty   = tid >> 4;     // 0..15  -> row group

    // A load mapping: 128 rows x 8 cols per chunk = 256 float4
    const int arow = tid >> 1;            // 0..127
    const int acol = (tid & 1) * 4;       // 0 or 4
    // B load mapping: 8 rows x 128 cols = 256 float4
    const int brow = tid >> 5;            // 0..7
    const int bcol = (tid & 31) * 4;      // 0..124

    float acc[TM][TN];
    #pragma unroll
    for (int i = 0; i < TM; i++)
        #pragma unroll
        for (int j = 0; j < TN; j++)
            acc[i][j] = 0.f;

    const int K = IN_F, N = OUT_F;

    for (int k0 = 0; k0 < K; k0 += BK) {
        float4 av = make_float4(0.f, 0.f, 0.f, 0.f);
        if (row0 + arow < M)
            av = *reinterpret_cast<const float4*>(
                     A + (size_t)(row0 + arow) * K + k0 + acol);
        As[acol + 0][arow] = av.x;
        As[acol + 1][arow] = av.y;
        As[acol + 2][arow] = av.z;
        As[acol + 3][arow] = av.w;

        float4 bv = *reinterpret_cast<const float4*>(
                        B + (size_t)(k0 + brow) * N + bcol);
        *reinterpret_cast<float4*>(&Bs[brow][bcol]) = bv;

        __syncthreads();

        #pragma unroll
        for (int k = 0; k < BK; k++) {
            float a[TM], b[TN];
            #pragma unroll
            for (int i = 0; i < TM; i++) a[i] = As[k][ty * TM + i];
            #pragma unroll
            for (int j = 0; j < TN; j++) b[j] = Bs[k][tx * TN + j];
            #pragma unroll
            for (int i = 0; i < TM; i++)
                #pragma unroll
                for (int j = 0; j < TN; j++)
                    acc[i][j] += a[i] * b[j];
        }
        __syncthreads();
    }

    #pragma unroll
    for (int i = 0; i < TM; i++) {
        int r = row0 + ty * TM + i;
        if (r < M) {
            float4* p = reinterpret_cast<float4*>(
                            g_support + (size_t)r * OUT_F + tx * TN);
            p[0] = make_float4(acc[i][0], acc[i][1], acc[i][2], acc[i][3]);
            p[1] = make_float4(acc[i][4], acc[i][5], acc[i][6], acc[i][7]);
        }
    }
}

// ---------------------------------------------------------------------------
// Kernel 2: build CSR row pointers from sorted edge_dst.
// row_start[n] = first edge e with dst[e] >= n;  row_start[N] = E.
// One thread per edge boundary; gaps are tiny on average (N/E).
// ---------------------------------------------------------------------------
__global__ void build_row_start_kernel(const int* __restrict__ dst, int E, int N)
{
    int e = blockIdx.x * blockDim.x + threadIdx.x;
    if (e > E) return;
    if (e == 0) {
        int d1 = dst[0];
        for (int n = 0; n <= d1; n++) g_row_start[n] = 0;
    } else if (e == E) {
        int d0 = dst[E - 1];
        for (int n = d0 + 1; n <= N; n++) g_row_start[n] = E;
    } else {
        int d0 = dst[e - 1];
        int d1 = dst[e];
        for (int n = d0 + 1; n <= d1; n++) g_row_start[n] = e;
    }
}

// ---------------------------------------------------------------------------
// Kernel 3: per-node aggregation + bias + tanh (fused epilogue).
// One block of 128 threads per node; thread t owns output feature t.
// Gathers from g_support are warp-coalesced 128B segments; support fits L2.
// No atomics: each node's edge segment is owned by exactly one block.
// ---------------------------------------------------------------------------
__global__ __launch_bounds__(OUT_F)
void aggregate_kernel(const int*   __restrict__ src,
                      const float* __restrict__ val,
                      const float* __restrict__ bias,
                      float*       __restrict__ out)
{
    const int n = blockIdx.x;
    const int t = threadIdx.x;

    const int s = g_row_start[n];
    const int e = g_row_start[n + 1];

    float acc = 0.f;
    int i = s;
    // 4-way unroll: 4 independent gathers in flight (MLP) per iteration
    for (; i + 4 <= e; i += 4) {
        int   s0 = src[i],     s1 = src[i + 1], s2 = src[i + 2], s3 = src[i + 3];
        float v0 = val[i],     v1 = val[i + 1], v2 = val[i + 2], v3 = val[i + 3];
        float x0 = g_support[(size_t)s0 * OUT_F + t];
        float x1 = g_support[(size_t)s1 * OUT_F + t];
        float x2 = g_support[(size_t)s2 * OUT_F + t];
        float x3 = g_support[(size_t)s3 * OUT_F + t];
        acc += v0 * x0;
        acc += v1 * x1;
        acc += v2 * x2;
        acc += v3 * x3;
    }
    for (; i < e; i++)
        acc += val[i] * g_support[(size_t)src[i] * OUT_F + t];

    out[(size_t)n * OUT_F + t] = tanhf(acc + bias[t]);
}

// ---------------------------------------------------------------------------
// Launch
// ---------------------------------------------------------------------------
extern "C" void kernel_launch(void* const* d_in, const int* in_sizes, int n_in,
                              void* d_out, int out_size)
{
    const float* x        = (const float*)d_in[0];  // [N, 256]
    const float* weight   = (const float*)d_in[1];  // [256, 128]
    const float* bias     = (const float*)d_in[2];  // [128]
    const int*   edge_src = (const int*)  d_in[3];  // [E]
    const int*   edge_dst = (const int*)  d_in[4];  // [E]
    const float* edge_val = (const float*)d_in[5];  // [E]
    float*       out      = (float*)d_out;          // [N, 128]

    const int M = in_sizes[0] / IN_F;   // 100000
    const int E = in_sizes[3];          // 1600000

    // 1) support = X @ W
    {
        dim3 grid((M + BM - 1) / BM);
        sgemm_xw_kernel<<<grid, 256>>>(x, weight, M);
    }
    // 2) CSR row pointers from sorted dst
    {
        int threads = 256;
        int blocks  = (E + 1 + threads - 1) / threads;
        build_row_start_kernel<<<blocks, threads>>>(edge_dst, E, M);
    }
    // 3) gather + segment-sum + bias + tanh
    {
        aggregate_kernel<<<M, OUT_F>>>(edge_src, edge_val, bias, out);
    }
}

// round 3
// speedup vs baseline: 1.8701x; 1.8701x over previous
#include <cuda_runtime.h>
#include <cuda_bf16.h>
#include <cstdint>

#define IN_F   256
#define OUT_F  128
#define NNODES 100000

// Scratch: support = X @ W   [NNODES, OUT_F] fp32
__device__ float g_support[(size_t)NNODES * OUT_F];
__device__ int   g_row_start[NNODES + 1];

// ===========================================================================
// Helpers: ldmatrix / mma.sync (sm_80+ path -> HMMA on Blackwell)
// ===========================================================================
__device__ __forceinline__ uint32_t smem_u32(const void* p) {
    uint32_t a;
    asm("{ .reg .u64 t; cvta.to.shared.u64 t, %1; cvt.u32.u64 %0, t; }"
        : "=r"(a) : "l"(p));
    return a;
}

__device__ __forceinline__ void ldsm_x4(uint32_t* r, uint32_t addr) {
    asm volatile("ldmatrix.sync.aligned.m8n8.x4.shared.b16 {%0,%1,%2,%3}, [%4];"
                 : "=r"(r[0]), "=r"(r[1]), "=r"(r[2]), "=r"(r[3]) : "r"(addr));
}
__device__ __forceinline__ void ldsm_x4_t(uint32_t* r, uint32_t addr) {
    asm volatile("ldmatrix.sync.aligned.m8n8.x4.trans.shared.b16 {%0,%1,%2,%3}, [%4];"
                 : "=r"(r[0]), "=r"(r[1]), "=r"(r[2]), "=r"(r[3]) : "r"(addr));
}
__device__ __forceinline__ void mma_bf16(float* c, const uint32_t* a, const uint32_t* b) {
    asm volatile(
        "mma.sync.aligned.m16n8k16.row.col.f32.bf16.bf16.f32 "
        "{%0,%1,%2,%3}, {%4,%5,%6,%7}, {%8,%9}, {%0,%1,%2,%3};"
        : "+f"(c[0]), "+f"(c[1]), "+f"(c[2]), "+f"(c[3])
        : "r"(a[0]), "r"(a[1]), "r"(a[2]), "r"(a[3]), "r"(b[0]), "r"(b[1]));
}

__device__ __forceinline__ uint32_t pack_hi2(float x, float y) {
    __nv_bfloat16 hx = __float2bfloat16(x);
    __nv_bfloat16 hy = __float2bfloat16(y);
    return (uint32_t)__bfloat16_as_ushort(hx) | ((uint32_t)__bfloat16_as_ushort(hy) << 16);
}
__device__ __forceinline__ uint32_t pack_lo2(float x, float y) {
    __nv_bfloat16 hx = __float2bfloat16(x);
    __nv_bfloat16 hy = __float2bfloat16(y);
    __nv_bfloat16 lx = __float2bfloat16(x - __bfloat162float(hx));
    __nv_bfloat16 ly = __float2bfloat16(y - __bfloat162float(hy));
    return (uint32_t)__bfloat16_as_ushort(lx) | ((uint32_t)__bfloat16_as_ushort(ly) << 16);
}

// ===========================================================================
// Kernel 1: GEMM  support[M,128] = X[M,256] @ W[256,128]
// bf16 3-term split on tensor cores: C = Ahi*Bhi + Ahi*Blo + Alo*Bhi
// Block 128x128, 256 threads (8 warps, 2x4), warp tile 64x32, BK=32.
// SMEM bf16 tiles, padded strides (no swizzle needed for ldmatrix).
// ===========================================================================
#define BKC 32                       // fp32 k per chunk
#define A_STRIDE 40                  // bf16 elems per row (32 + 8 pad)
#define B_STRIDE 136                 // bf16 elems per row (128 + 8 pad)
#define SM_AHI 0
#define SM_ALO (128 * A_STRIDE * 2)              // 10240
#define SM_BHI (2 * 128 * A_STRIDE * 2)          // 20480
#define SM_BLO (SM_BHI + 32 * B_STRIDE * 2)      // 29184
#define SM_TOTAL (SM_BLO + 32 * B_STRIDE * 2)    // 37888

__global__ void __launch_bounds__(256, 1)
gemm_mma_kernel(const float* __restrict__ X, const float* __restrict__ W, int M)
{
    __shared__ __align__(16) char smem[SM_TOTAL];
    const uint32_t sb = smem_u32(smem);

    const int tid    = threadIdx.x;
    const int lane   = tid & 31;
    const int wid    = tid >> 5;
    const int warp_m = (wid & 1) * 64;   // 0 or 64
    const int warp_n = (wid >> 1) * 32;  // 0,32,64,96
    const int row0   = blockIdx.x << 7;

    float acc[4][4][4];
    #pragma unroll
    for (int i = 0; i < 4; i++)
        #pragma unroll
        for (int j = 0; j < 4; j++)
            #pragma unroll
            for (int q = 0; q < 4; q++) acc[i][j][q] = 0.f;

    // prefetch registers (chunk c fp32 tiles)
    float4 xa[4], wb[4];

    // --- load chunk 0 ---
    #pragma unroll
    for (int i = 0; i < 4; i++) {
        int idx = tid + i * 256;
        int r = idx >> 3, kq = idx & 7;        // A: row 0..127, k-quad 0..7
        int gr = row0 + r;
        xa[i] = (gr < M) ? *reinterpret_cast<const float4*>(X + (size_t)gr * IN_F + kq * 4)
                         : make_float4(0.f, 0.f, 0.f, 0.f);
        int kr = idx >> 5, cq = idx & 31;      // B: k-row 0..31, col-quad 0..31
        wb[i] = *reinterpret_cast<const float4*>(W + (size_t)kr * OUT_F + cq * 4);
    }

    for (int c = 0; c < IN_F / BKC; c++) {
        // --- convert & store current chunk to smem ---
        #pragma unroll
        for (int i = 0; i < 4; i++) {
            int idx = tid + i * 256;
            int r = idx >> 3, kq = idx & 7;
            uint32_t h0 = pack_hi2(xa[i].x, xa[i].y), h1 = pack_hi2(xa[i].z, xa[i].w);
            uint32_t l0 = pack_lo2(xa[i].x, xa[i].y), l1 = pack_lo2(xa[i].z, xa[i].w);
            uint32_t a_off = (uint32_t)(r * (A_STRIDE * 2) + kq * 8);
            asm volatile("st.shared.v2.b32 [%0], {%1,%2};" :: "r"(sb + SM_AHI + a_off), "r"(h0), "r"(h1) : "memory");
            asm volatile("st.shared.v2.b32 [%0], {%1,%2};" :: "r"(sb + SM_ALO + a_off), "r"(l0), "r"(l1) : "memory");

            int kr = idx >> 5, cq = idx & 31;
            uint32_t bh0 = pack_hi2(wb[i].x, wb[i].y), bh1 = pack_hi2(wb[i].z, wb[i].w);
            uint32_t bl0 = pack_lo2(wb[i].x, wb[i].y), bl1 = pack_lo2(wb[i].z, wb[i].w);
            uint32_t b_off = (uint32_t)(kr * (B_STRIDE * 2) + cq * 8);
            asm volatile("st.shared.v2.b32 [%0], {%1,%2};" :: "r"(sb + SM_BHI + b_off), "r"(bh0), "r"(bh1) : "memory");
            asm volatile("st.shared.v2.b32 [%0], {%1,%2};" :: "r"(sb + SM_BLO + b_off), "r"(bl0), "r"(bl1) : "memory");
        }
        __syncthreads();

        // --- prefetch next chunk (overlaps with MMA below) ---
        if (c + 1 < IN_F / BKC) {
            int k0n = (c + 1) * BKC;
            #pragma unroll
            for (int i = 0; i < 4; i++) {
                int idx = tid + i * 256;
                int r = idx >> 3, kq = idx & 7;
                int gr = row0 + r;
                xa[i] = (gr < M) ? *reinterpret_cast<const float4*>(X + (size_t)gr * IN_F + k0n + kq * 4)
                                 : make_float4(0.f, 0.f, 0.f, 0.f);
                int kr = idx >> 5, cq = idx & 31;
                wb[i] = *reinterpret_cast<const float4*>(W + (size_t)(k0n + kr) * OUT_F + cq * 4);
            }
        }

        // --- MMA over this chunk: 2 k16 steps ---
        #pragma unroll
        for (int ks = 0; ks < 2; ks++) {
            uint32_t ah[4][4], al[4][4], bh[2][4], bl[2][4];
            const uint32_t a_col = (uint32_t)((ks * 16 + (lane >> 4) * 8) * 2);
            #pragma unroll
            for (int mi = 0; mi < 4; mi++) {
                uint32_t ar = (uint32_t)((warp_m + mi * 16 + (lane & 15)) * (A_STRIDE * 2)) + a_col;
                ldsm_x4(ah[mi], sb + SM_AHI + ar);
                ldsm_x4(al[mi], sb + SM_ALO + ar);
            }
            const uint32_t b_row = (uint32_t)((ks * 16 + (lane & 7) + ((lane >> 3) & 1) * 8) * (B_STRIDE * 2));
            #pragma unroll
            for (int nj = 0; nj < 2; nj++) {
                uint32_t br = b_row + (uint32_t)((warp_n + nj * 16 + (lane >> 4) * 8) * 2);
                ldsm_x4_t(bh[nj], sb + SM_BHI + br);
                ldsm_x4_t(bl[nj], sb + SM_BLO + br);
            }
            #pragma unroll
            for (int mi = 0; mi < 4; mi++) {
                #pragma unroll
                for (int nj = 0; nj < 4; nj++) {
                    uint32_t bhf[2] = { bh[nj >> 1][(nj & 1) * 2], bh[nj >> 1][(nj & 1) * 2 + 1] };
                    uint32_t blf[2] = { bl[nj >> 1][(nj & 1) * 2], bl[nj >> 1][(nj & 1) * 2 + 1] };
                    mma_bf16(acc[mi][nj], ah[mi], bhf);
                    mma_bf16(acc[mi][nj], ah[mi], blf);
                    mma_bf16(acc[mi][nj], al[mi], bhf);
                }
            }
        }
        __syncthreads();
    }

    // --- epilogue: write accumulators to g_support ---
    #pragma unroll
    for (int mi = 0; mi < 4; mi++) {
        int r_lo = row0 + warp_m + mi * 16 + (lane >> 2);
        int r_hi = r_lo + 8;
        #pragma unroll
        for (int nj = 0; nj < 4; nj++) {
            int col = warp_n + nj * 8 + (lane & 3) * 2;
            if (r_lo < M)
                *reinterpret_cast<float2*>(g_support + (size_t)r_lo * OUT_F + col) =
                    make_float2(acc[mi][nj][0], acc[mi][nj][1]);
            if (r_hi < M)
                *reinterpret_cast<float2*>(g_support + (size_t)r_hi * OUT_F + col) =
                    make_float2(acc[mi][nj][2], acc[mi][nj][3]);
        }
    }
}

// ===========================================================================
// Kernel 2: CSR row pointers from sorted edge_dst
// ===========================================================================
__global__ void build_row_start_kernel(const int* __restrict__ dst, int E, int N)
{
    int e = blockIdx.x * blockDim.x + threadIdx.x;
    if (e > E) return;
    if (e == 0) {
        int d1 = dst[0];
        for (int n = 0; n <= d1; n++) g_row_start[n] = 0;
    } else if (e == E) {
        int d0 = dst[E - 1];
        for (int n = d0 + 1; n <= N; n++) g_row_start[n] = E;
    } else {
        int d0 = dst[e - 1];
        int d1 = dst[e];
        for (int n = d0 + 1; n <= d1; n++) g_row_start[n] = e;
    }
}

// ===========================================================================
// Kernel 3: aggregation + bias + tanh.
// 128 threads = 2 nodes/block; 64 threads per node, float2 per thread.
// ===========================================================================
__global__ __launch_bounds__(128)
void aggregate_kernel(const int*   __restrict__ src,
                      const float* __restrict__ val,
                      const float* __restrict__ bias,
                      float*       __restrict__ out,
                      int N)
{
    const int n = blockIdx.x * 2 + (threadIdx.x >> 6);
    if (n >= N) return;
    const int t2 = (threadIdx.x & 63) * 2;

    const int s = g_row_start[n];
    const int e = g_row_start[n + 1];

    float ax = 0.f, ay = 0.f;
    int i = s;
    for (; i + 4 <= e; i += 4) {
        int   s0 = src[i],     s1 = src[i + 1], s2 = src[i + 2], s3 = src[i + 3];
        float v0 = val[i],     v1 = val[i + 1], v2 = val[i + 2], v3 = val[i + 3];
        float2 x0 = *reinterpret_cast<const float2*>(g_support + (size_t)s0 * OUT_F + t2);
        float2 x1 = *reinterpret_cast<const float2*>(g_support + (size_t)s1 * OUT_F + t2);
        float2 x2 = *reinterpret_cast<const float2*>(g_support + (size_t)s2 * OUT_F + t2);
        float2 x3 = *reinterpret_cast<const float2*>(g_support + (size_t)s3 * OUT_F + t2);
        ax += v0 * x0.x; ay += v0 * x0.y;
        ax += v1 * x1.x; ay += v1 * x1.y;
        ax += v2 * x2.x; ay += v2 * x2.y;
        ax += v3 * x3.x; ay += v3 * x3.y;
    }
    for (; i < e; i++) {
        float v = val[i];
        float2 xv = *reinterpret_cast<const float2*>(g_support + (size_t)src[i] * OUT_F + t2);
        ax += v * xv.x; ay += v * xv.y;
    }

    float2 b = *reinterpret_cast<const float2*>(bias + t2);
    *reinterpret_cast<float2*>(out + (size_t)n * OUT_F + t2) =
        make_float2(tanhf(ax + b.x), tanhf(ay + b.y));
}

// ===========================================================================
// Launch
// ===========================================================================
extern "C" void kernel_launch(void* const* d_in, const int* in_sizes, int n_in,
                              void* d_out, int out_size)
{
    const float* x        = (const float*)d_in[0];
    const float* weight   = (const float*)d_in[1];
    const float* bias     = (const float*)d_in[2];
    const int*   edge_src = (const int*)  d_in[3];
    const int*   edge_dst = (const int*)  d_in[4];
    const float* edge_val = (const float*)d_in[5];
    float*       out      = (float*)d_out;

    const int M = in_sizes[0] / IN_F;   // 100000
    const int E = in_sizes[3];          // 1600000

    // 1) support = X @ W  (tensor cores via mma.sync, bf16 3-term split)
    {
        dim3 grid((M + 127) / 128);
        gemm_mma_kernel<<<grid, 256>>>(x, weight, M);
    }
    // 2) CSR row pointers from sorted dst
    {
        int threads = 256;
        int blocks  = (E + 1 + threads - 1) / threads;
        build_row_start_kernel<<<blocks, threads>>>(edge_dst, E, M);
    }
    // 3) gather + segment-sum + bias + tanh
    {
        aggregate_kernel<<<(M + 1) / 2, 128>>>(edge_src, edge_val, bias, out, M);
    }
}

// round 4
// speedup vs baseline: 1.9628x; 1.0496x over previous
#include <cuda_runtime.h>
#include <cuda_bf16.h>
#include <cuda_fp16.h>
#include <cstdint>

#define IN_F   256
#define OUT_F  128
#define NNODES 100000

// support = X @ W stored as fp16 (halves aggregate gather traffic)
__device__ __half2 g_support_h[(size_t)NNODES * (OUT_F / 2)];
__device__ int     g_row_start[NNODES + 1];
// Preconverted weight split (bf16 hi/lo), done once
__device__ __nv_bfloat16 g_whi[IN_F * OUT_F];
__device__ __nv_bfloat16 g_wlo[IN_F * OUT_F];

// ===========================================================================
// Helpers
// ===========================================================================
__device__ __forceinline__ uint32_t smem_u32(const void* p) {
    uint32_t a;
    asm("{ .reg .u64 t; cvta.to.shared.u64 t, %1; cvt.u32.u64 %0, t; }"
        : "=r"(a) : "l"(p));
    return a;
}
__device__ __forceinline__ void ldsm_x4(uint32_t* r, uint32_t addr) {
    asm volatile("ldmatrix.sync.aligned.m8n8.x4.shared.b16 {%0,%1,%2,%3}, [%4];"
                 : "=r"(r[0]), "=r"(r[1]), "=r"(r[2]), "=r"(r[3]) : "r"(addr));
}
__device__ __forceinline__ void ldsm_x4_t(uint32_t* r, uint32_t addr) {
    asm volatile("ldmatrix.sync.aligned.m8n8.x4.trans.shared.b16 {%0,%1,%2,%3}, [%4];"
                 : "=r"(r[0]), "=r"(r[1]), "=r"(r[2]), "=r"(r[3]) : "r"(addr));
}
__device__ __forceinline__ void mma_bf16(float* c, const uint32_t* a, const uint32_t* b) {
    asm volatile(
        "mma.sync.aligned.m16n8k16.row.col.f32.bf16.bf16.f32 "
        "{%0,%1,%2,%3}, {%4,%5,%6,%7}, {%8,%9}, {%0,%1,%2,%3};"
        : "+f"(c[0]), "+f"(c[1]), "+f"(c[2]), "+f"(c[3])
        : "r"(a[0]), "r"(a[1]), "r"(a[2]), "r"(a[3]), "r"(b[0]), "r"(b[1]));
}
__device__ __forceinline__ uint32_t pack_hi2(float x, float y) {
    __nv_bfloat16 hx = __float2bfloat16(x);
    __nv_bfloat16 hy = __float2bfloat16(y);
    return (uint32_t)__bfloat16_as_ushort(hx) | ((uint32_t)__bfloat16_as_ushort(hy) << 16);
}
__device__ __forceinline__ uint32_t pack_lo2(float x, float y) {
    __nv_bfloat16 hx = __float2bfloat16(x);
    __nv_bfloat16 hy = __float2bfloat16(y);
    __nv_bfloat16 lx = __float2bfloat16(x - __bfloat162float(hx));
    __nv_bfloat16 ly = __float2bfloat16(y - __bfloat162float(hy));
    return (uint32_t)__bfloat16_as_ushort(lx) | ((uint32_t)__bfloat16_as_ushort(ly) << 16);
}

// ===========================================================================
// Kernel 0: one-time W split (fp32 -> bf16 hi/lo)
// ===========================================================================
__global__ void convert_w_kernel(const float* __restrict__ W)
{
    int i = blockIdx.x * 256 + threadIdx.x;
    if (i < IN_F * OUT_F) {
        float w = W[i];
        __nv_bfloat16 hi = __float2bfloat16(w);
        __nv_bfloat16 lo = __float2bfloat16(w - __bfloat162float(hi));
        g_whi[i] = hi;
        g_wlo[i] = lo;
    }
}

// ===========================================================================
// Kernel 1: GEMM  support[M,128] = X[M,256] @ W[256,128] (3-term bf16 split)
// Block 128x128, 8 warps (2x4), warp tile 64x32, BK=32 fp32.
// B (whole 256 k-rows, hi+lo) resident in SMEM; A tiles double-buffered.
// One __syncthreads per chunk; LDG prefetch + convert overlap MMA.
// ===========================================================================
#define BKC 32
#define A_STRIDE 40                  // bf16 per row (32+8 pad)
#define B_STRIDE 136                 // bf16 per row (128+8 pad)
#define A_BUF_BYTES (128 * A_STRIDE * 2 * 2)      // hi+lo per buf = 20480
#define SM_A   0                                   // 2 bufs = 40960
#define SM_BH  (2 * A_BUF_BYTES)                   // 40960
#define SM_BL  (SM_BH + IN_F * B_STRIDE * 2)       // +69632 = 110592
#define SM_TOTAL (SM_BL + IN_F * B_STRIDE * 2)     // 180224

__global__ void __launch_bounds__(256, 1)
gemm_mma_kernel(const float* __restrict__ X, int M)
{
    extern __shared__ __align__(16) char smem[];
    const uint32_t sb = smem_u32(smem);

    const int tid    = threadIdx.x;
    const int lane   = tid & 31;
    const int wid    = tid >> 5;
    const int warp_m = (wid & 1) * 64;
    const int warp_n = (wid >> 1) * 32;
    const int row0   = blockIdx.x << 7;

    // ---- prologue: load preconverted W (hi/lo) into SMEM ----
    {
        const uint4* whi = reinterpret_cast<const uint4*>(g_whi);
        const uint4* wlo = reinterpret_cast<const uint4*>(g_wlo);
        #pragma unroll
        for (int i = 0; i < 16; i++) {
            int e = tid + i * 256;          // 4096 units of 8 bf16
            int k = e >> 4, u = e & 15;
            uint4 h = whi[(size_t)k * 16 + u];
            uint4 l = wlo[(size_t)k * 16 + u];
            uint32_t off = (uint32_t)(k * (B_STRIDE * 2) + u * 16);
            asm volatile("st.shared.v4.b32 [%0], {%1,%2,%3,%4};"
                         :: "r"(sb + SM_BH + off), "r"(h.x), "r"(h.y), "r"(h.z), "r"(h.w) : "memory");
            asm volatile("st.shared.v4.b32 [%0], {%1,%2,%3,%4};"
                         :: "r"(sb + SM_BL + off), "r"(l.x), "r"(l.y), "r"(l.z), "r"(l.w) : "memory");
        }
    }

    float acc[4][4][4];
    #pragma unroll
    for (int i = 0; i < 4; i++)
        #pragma unroll
        for (int j = 0; j < 4; j++)
            #pragma unroll
            for (int q = 0; q < 4; q++) acc[i][j][q] = 0.f;

    const int a_r  = tid >> 3;        // 0..31 (row, stepped by 32 over i)
    const int a_kq = tid & 7;         // k-quad within chunk

    float4 xa[4];
    // load A chunk 0
    #pragma unroll
    for (int i = 0; i < 4; i++) {
        int r  = a_r + i * 32;
        int gr = row0 + r;
        xa[i] = (gr < M) ? *reinterpret_cast<const float4*>(X + (size_t)gr * IN_F + a_kq * 4)
                         : make_float4(0.f, 0.f, 0.f, 0.f);
    }
    // convert/store chunk 0 into buf 0
    #pragma unroll
    for (int i = 0; i < 4; i++) {
        int r = a_r + i * 32;
        uint32_t h0 = pack_hi2(xa[i].x, xa[i].y), h1 = pack_hi2(xa[i].z, xa[i].w);
        uint32_t l0 = pack_lo2(xa[i].x, xa[i].y), l1 = pack_lo2(xa[i].z, xa[i].w);
        uint32_t off = (uint32_t)(r * (A_STRIDE * 2) + a_kq * 8);
        asm volatile("st.shared.v2.b32 [%0], {%1,%2};" :: "r"(sb + SM_A + off), "r"(h0), "r"(h1) : "memory");
        asm volatile("st.shared.v2.b32 [%0], {%1,%2};" :: "r"(sb + SM_A + 10240 + off), "r"(l0), "r"(l1) : "memory");
    }
    __syncthreads();

    for (int c = 0; c < IN_F / BKC; c++) {
        const uint32_t abuf = sb + SM_A + (uint32_t)(c & 1) * A_BUF_BYTES;
        const bool more = (c + 1 < IN_F / BKC);

        // prefetch next A chunk (LDG latency hidden behind MMA)
        if (more) {
            int k0n = (c + 1) * BKC;
            #pragma unroll
            for (int i = 0; i < 4; i++) {
                int r  = a_r + i * 32;
                int gr = row0 + r;
                xa[i] = (gr < M) ? *reinterpret_cast<const float4*>(X + (size_t)gr * IN_F + k0n + a_kq * 4)
                                 : make_float4(0.f, 0.f, 0.f, 0.f);
            }
        }

        // ---- MMA over chunk c ----
        #pragma unroll
        for (int ks = 0; ks < 2; ks++) {
            uint32_t ah[4][4], al[4][4], bh[2][4], bl[2][4];
            const uint32_t a_col = (uint32_t)((ks * 16 + (lane >> 4) * 8) * 2);
            #pragma unroll
            for (int mi = 0; mi < 4; mi++) {
                uint32_t ar = (uint32_t)((warp_m + mi * 16 + (lane & 15)) * (A_STRIDE * 2)) + a_col;
                ldsm_x4(ah[mi], abuf + ar);
                ldsm_x4(al[mi], abuf + 10240 + ar);
            }
            const uint32_t b_row =
                (uint32_t)((c * 32 + ks * 16 + (lane & 7) + ((lane >> 3) & 1) * 8) * (B_STRIDE * 2));
            #pragma unroll
            for (int nj = 0; nj < 2; nj++) {
                uint32_t br = b_row + (uint32_t)((warp_n + nj * 16 + (lane >> 4) * 8) * 2);
                ldsm_x4_t(bh[nj], sb + SM_BH + br);
                ldsm_x4_t(bl[nj], sb + SM_BL + br);
            }
            #pragma unroll
            for (int mi = 0; mi < 4; mi++) {
                #pragma unroll
                for (int nj = 0; nj < 4; nj++) {
                    uint32_t bhf[2] = { bh[nj >> 1][(nj & 1) * 2], bh[nj >> 1][(nj & 1) * 2 + 1] };
                    uint32_t blf[2] = { bl[nj >> 1][(nj & 1) * 2], bl[nj >> 1][(nj & 1) * 2 + 1] };
                    mma_bf16(acc[mi][nj], ah[mi], bhf);
                    mma_bf16(acc[mi][nj], ah[mi], blf);
                    mma_bf16(acc[mi][nj], al[mi], bhf);
                }
            }
        }

        // convert/store next chunk into the other buffer
        if (more) {
            const uint32_t nbuf = sb + SM_A + (uint32_t)((c + 1) & 1) * A_BUF_BYTES;
            #pragma unroll
            for (int i = 0; i < 4; i++) {
                int r = a_r + i * 32;
                uint32_t h0 = pack_hi2(xa[i].x, xa[i].y), h1 = pack_hi2(xa[i].z, xa[i].w);
                uint32_t l0 = pack_lo2(xa[i].x, xa[i].y), l1 = pack_lo2(xa[i].z, xa[i].w);
                uint32_t off = (uint32_t)(r * (A_STRIDE * 2) + a_kq * 8);
                asm volatile("st.shared.v2.b32 [%0], {%1,%2};" :: "r"(nbuf + off), "r"(h0), "r"(h1) : "memory");
                asm volatile("st.shared.v2.b32 [%0], {%1,%2};" :: "r"(nbuf + 10240 + off), "r"(l0), "r"(l1) : "memory");
            }
        }
        __syncthreads();
    }

    // ---- epilogue: accumulators -> g_support_h (fp16) ----
    #pragma unroll
    for (int mi = 0; mi < 4; mi++) {
        int r_lo = row0 + warp_m + mi * 16 + (lane >> 2);
        int r_hi = r_lo + 8;
        #pragma unroll
        for (int nj = 0; nj < 4; nj++) {
            int col = warp_n + nj * 8 + (lane & 3) * 2;   // even
            if (r_lo < M)
                g_support_h[(size_t)r_lo * (OUT_F / 2) + (col >> 1)] =
                    __floats2half2_rn(acc[mi][nj][0], acc[mi][nj][1]);
            if (r_hi < M)
                g_support_h[(size_t)r_hi * (OUT_F / 2) + (col >> 1)] =
                    __floats2half2_rn(acc[mi][nj][2], acc[mi][nj][3]);
        }
    }
}

// ===========================================================================
// Kernel 2: CSR row pointers from sorted edge_dst
// ===========================================================================
__global__ void build_row_start_kernel(const int* __restrict__ dst, int E, int N)
{
    int e = blockIdx.x * blockDim.x + threadIdx.x;
    if (e > E) return;
    if (e == 0) {
        int d1 = dst[0];
        for (int n = 0; n <= d1; n++) g_row_start[n] = 0;
    } else if (e == E) {
        int d0 = dst[E - 1];
        for (int n = d0 + 1; n <= N; n++) g_row_start[n] = E;
    } else {
        int d0 = dst[e - 1];
        int d1 = dst[e];
        for (int n = d0 + 1; n <= d1; n++) g_row_start[n] = e;
    }
}

// ===========================================================================
// Kernel 3: aggregation + bias + tanh (fp16 gather, fp32 accumulate)
// 128 threads = 2 nodes/block; 64 threads/node, one half2 (2 cols) each.
// ===========================================================================
__global__ __launch_bounds__(128)
void aggregate_kernel(const int*   __restrict__ src,
                      const float* __restrict__ val,
                      const float* __restrict__ bias,
                      float*       __restrict__ out,
                      int N)
{
    const int n = blockIdx.x * 2 + (threadIdx.x >> 6);
    if (n >= N) return;
    const int t = threadIdx.x & 63;            // half2 index; cols 2t, 2t+1

    const int s = g_row_start[n];
    const int e = g_row_start[n + 1];

    float ax = 0.f, ay = 0.f;
    int i = s;
    for (; i + 4 <= e; i += 4) {
        int   s0 = src[i],     s1 = src[i + 1], s2 = src[i + 2], s3 = src[i + 3];
        float v0 = val[i],     v1 = val[i + 1], v2 = val[i + 2], v3 = val[i + 3];
        float2 x0 = __half22float2(g_support_h[(size_t)s0 * 64 + t]);
        float2 x1 = __half22float2(g_support_h[(size_t)s1 * 64 + t]);
        float2 x2 = __half22float2(g_support_h[(size_t)s2 * 64 + t]);
        float2 x3 = __half22float2(g_support_h[(size_t)s3 * 64 + t]);
        ax += v0 * x0.x; ay += v0 * x0.y;
        ax += v1 * x1.x; ay += v1 * x1.y;
        ax += v2 * x2.x; ay += v2 * x2.y;
        ax += v3 * x3.x; ay += v3 * x3.y;
    }
    for (; i < e; i++) {
        float v = val[i];
        float2 xv = __half22float2(g_support_h[(size_t)src[i] * 64 + t]);
        ax += v * xv.x; ay += v * xv.y;
    }

    float2 b = *reinterpret_cast<const float2*>(bias + t * 2);
    *reinterpret_cast<float2*>(out + (size_t)n * OUT_F + t * 2) =
        make_float2(tanhf(ax + b.x), tanhf(ay + b.y));
}

// ===========================================================================
// Launch
// ===========================================================================
extern "C" void kernel_launch(void* const* d_in, const int* in_sizes, int n_in,
                              void* d_out, int out_size)
{
    const float* x        = (const float*)d_in[0];
    const float* weight   = (const float*)d_in[1];
    const float* bias     = (const float*)d_in[2];
    const int*   edge_src = (const int*)  d_in[3];
    const int*   edge_dst = (const int*)  d_in[4];
    const float* edge_val = (const float*)d_in[5];
    float*       out      = (float*)d_out;

    const int M = in_sizes[0] / IN_F;   // 100000
    const int E = in_sizes[3];          // 1600000

    static bool attr_done = false;
    if (!attr_done) {
        cudaFuncSetAttribute(gemm_mma_kernel,
                             cudaFuncAttributeMaxDynamicSharedMemorySize, SM_TOTAL);
        attr_done = true;
    }

    // 0) one-time-per-call W split (cheap, 32K elems)
    convert_w_kernel<<<(IN_F * OUT_F + 255) / 256, 256>>>(weight);
    // 1) support = X @ W on tensor cores
    gemm_mma_kernel<<<(M + 127) / 128, 256, SM_TOTAL>>>(x, M);
    // 2) CSR row pointers
    {
        int threads = 256;
        int blocks  = (E + 1 + threads - 1) / threads;
        build_row_start_kernel<<<blocks, threads>>>(edge_dst, E, M);
    }
    // 3) gather + segment-sum + bias + tanh
    aggregate_kernel<<<(M + 1) / 2, 128>>>(edge_src, edge_val, bias, out, M);
}

// round 5
// speedup vs baseline: 3.2365x; 1.6489x over previous
#include <cuda_runtime.h>
#include <cuda_bf16.h>
#include <cuda_fp16.h>
#include <cstdint>

#define IN_F   256
#define OUT_F  128
#define NNODES 100000

// support = X @ W stored as fp16 (halves aggregate gather traffic)
__device__ __half2 g_support_h[(size_t)NNODES * (OUT_F / 2)];
__device__ int     g_row_start[NNODES + 1];
// Preconverted weight (fp16), done once per call
__device__ __half  g_wh[IN_F * OUT_F];

// ===========================================================================
// Helpers
// ===========================================================================
__device__ __forceinline__ uint32_t smem_u32(const void* p) {
    uint32_t a;
    asm("{ .reg .u64 t; cvta.to.shared.u64 t, %1; cvt.u32.u64 %0, t; }"
        : "=r"(a) : "l"(p));
    return a;
}
__device__ __forceinline__ void ldsm_x4(uint32_t* r, uint32_t addr) {
    asm volatile("ldmatrix.sync.aligned.m8n8.x4.shared.b16 {%0,%1,%2,%3}, [%4];"
                 : "=r"(r[0]), "=r"(r[1]), "=r"(r[2]), "=r"(r[3]) : "r"(addr));
}
__device__ __forceinline__ void ldsm_x4_t(uint32_t* r, uint32_t addr) {
    asm volatile("ldmatrix.sync.aligned.m8n8.x4.trans.shared.b16 {%0,%1,%2,%3}, [%4];"
                 : "=r"(r[0]), "=r"(r[1]), "=r"(r[2]), "=r"(r[3]) : "r"(addr));
}
__device__ __forceinline__ void mma_fp16(float* c, const uint32_t* a, const uint32_t* b) {
    asm volatile(
        "mma.sync.aligned.m16n8k16.row.col.f32.f16.f16.f32 "
        "{%0,%1,%2,%3}, {%4,%5,%6,%7}, {%8,%9}, {%0,%1,%2,%3};"
        : "+f"(c[0]), "+f"(c[1]), "+f"(c[2]), "+f"(c[3])
        : "r"(a[0]), "r"(a[1]), "r"(a[2]), "r"(a[3]), "r"(b[0]), "r"(b[1]));
}
__device__ __forceinline__ uint32_t packh2(float x, float y) {
    __half2 h = __floats2half2_rn(x, y);
    return *reinterpret_cast<uint32_t*>(&h);
}

// ===========================================================================
// Kernel 0: one-time W convert (fp32 -> fp16)
// ===========================================================================
__global__ void convert_w_kernel(const float* __restrict__ W)
{
    int i = blockIdx.x * 256 + threadIdx.x;
    if (i < IN_F * OUT_F)
        g_wh[i] = __float2half_rn(W[i]);
}

// ===========================================================================
// Kernel 1: GEMM  support[M,128] = X[M,256] @ W[256,128], fp16 inputs.
// Block 128x128, 8 warps (2x4), warp tile 64x32, BK=32 fp32.
// Whole W resident in SMEM (fp16); A tiles double-buffered (fp16).
// 90 KB smem -> 2 CTAs/SM; one __syncthreads per chunk.
// ===========================================================================
#define BKC 32
#define A_STRIDE 40                  // fp16 per row (32+8 pad)
#define B_STRIDE 136                 // fp16 per row (128+8 pad)
#define A_BUF_BYTES (128 * A_STRIDE * 2)          // 10240 per buffer
#define SM_A   0                                   // 2 bufs = 20480
#define SM_B   (2 * A_BUF_BYTES)                   // 20480
#define SM_TOTAL (SM_B + IN_F * B_STRIDE * 2)      // 20480 + 69632 = 90112

__global__ void __launch_bounds__(256, 2)
gemm_mma_kernel(const float* __restrict__ X, int M)
{
    extern __shared__ __align__(16) char smem[];
    const uint32_t sb = smem_u32(smem);

    const int tid    = threadIdx.x;
    const int lane   = tid & 31;
    const int wid    = tid >> 5;
    const int warp_m = (wid & 1) * 64;
    const int warp_n = (wid >> 1) * 32;
    const int row0   = blockIdx.x << 7;

    // ---- prologue: W (fp16) -> SMEM, 256 k-rows resident ----
    {
        const uint4* wp = reinterpret_cast<const uint4*>(g_wh);
        #pragma unroll
        for (int i = 0; i < 16; i++) {
            int e = tid + i * 256;          // 4096 units of 8 fp16
            int k = e >> 4, u = e & 15;
            uint4 h = wp[(size_t)k * 16 + u];
            uint32_t off = (uint32_t)(k * (B_STRIDE * 2) + u * 16);
            asm volatile("st.shared.v4.b32 [%0], {%1,%2,%3,%4};"
                         :: "r"(sb + SM_B + off), "r"(h.x), "r"(h.y), "r"(h.z), "r"(h.w) : "memory");
        }
    }

    float acc[4][4][4];
    #pragma unroll
    for (int i = 0; i < 4; i++)
        #pragma unroll
        for (int j = 0; j < 4; j++)
            #pragma unroll
            for (int q = 0; q < 4; q++) acc[i][j][q] = 0.f;

    const int a_r  = tid >> 3;        // 0..31 (+32*i)
    const int a_kq = tid & 7;

    float4 xa[4];
    #pragma unroll
    for (int i = 0; i < 4; i++) {
        int gr = row0 + a_r + i * 32;
        xa[i] = (gr < M) ? *reinterpret_cast<const float4*>(X + (size_t)gr * IN_F + a_kq * 4)
                         : make_float4(0.f, 0.f, 0.f, 0.f);
    }
    #pragma unroll
    for (int i = 0; i < 4; i++) {
        int r = a_r + i * 32;
        uint32_t h0 = packh2(xa[i].x, xa[i].y), h1 = packh2(xa[i].z, xa[i].w);
        uint32_t off = (uint32_t)(r * (A_STRIDE * 2) + a_kq * 8);
        asm volatile("st.shared.v2.b32 [%0], {%1,%2};" :: "r"(sb + SM_A + off), "r"(h0), "r"(h1) : "memory");
    }
    __syncthreads();

    for (int c = 0; c < IN_F / BKC; c++) {
        const uint32_t abuf = sb + SM_A + (uint32_t)(c & 1) * A_BUF_BYTES;
        const bool more = (c + 1 < IN_F / BKC);

        if (more) {
            int k0n = (c + 1) * BKC;
            #pragma unroll
            for (int i = 0; i < 4; i++) {
                int gr = row0 + a_r + i * 32;
                xa[i] = (gr < M) ? *reinterpret_cast<const float4*>(X + (size_t)gr * IN_F + k0n + a_kq * 4)
                                 : make_float4(0.f, 0.f, 0.f, 0.f);
            }
        }

        #pragma unroll
        for (int ks = 0; ks < 2; ks++) {
            uint32_t ah[4][4], bh[2][4];
            const uint32_t a_col = (uint32_t)((ks * 16 + (lane >> 4) * 8) * 2);
            #pragma unroll
            for (int mi = 0; mi < 4; mi++) {
                uint32_t ar = (uint32_t)((warp_m + mi * 16 + (lane & 15)) * (A_STRIDE * 2)) + a_col;
                ldsm_x4(ah[mi], abuf + ar);
            }
            const uint32_t b_row =
                (uint32_t)((c * 32 + ks * 16 + (lane & 7) + ((lane >> 3) & 1) * 8) * (B_STRIDE * 2));
            #pragma unroll
            for (int nj = 0; nj < 2; nj++) {
                uint32_t br = b_row + (uint32_t)((warp_n + nj * 16 + (lane >> 4) * 8) * 2);
                ldsm_x4_t(bh[nj], sb + SM_B + br);
            }
            #pragma unroll
            for (int mi = 0; mi < 4; mi++) {
                #pragma unroll
                for (int nj = 0; nj < 4; nj++) {
                    uint32_t bf[2] = { bh[nj >> 1][(nj & 1) * 2], bh[nj >> 1][(nj & 1) * 2 + 1] };
                    mma_fp16(acc[mi][nj], ah[mi], bf);
                }
            }
        }

        if (more) {
            const uint32_t nbuf = sb + SM_A + (uint32_t)((c + 1) & 1) * A_BUF_BYTES;
            #pragma unroll
            for (int i = 0; i < 4; i++) {
                int r = a_r + i * 32;
                uint32_t h0 = packh2(xa[i].x, xa[i].y), h1 = packh2(xa[i].z, xa[i].w);
                uint32_t off = (uint32_t)(r * (A_STRIDE * 2) + a_kq * 8);
                asm volatile("st.shared.v2.b32 [%0], {%1,%2};" :: "r"(nbuf + off), "r"(h0), "r"(h1) : "memory");
            }
        }
        __syncthreads();
    }

    // ---- epilogue: accumulators -> g_support_h (fp16) ----
    #pragma unroll
    for (int mi = 0; mi < 4; mi++) {
        int r_lo = row0 + warp_m + mi * 16 + (lane >> 2);
        int r_hi = r_lo + 8;
        #pragma unroll
        for (int nj = 0; nj < 4; nj++) {
            int col = warp_n + nj * 8 + (lane & 3) * 2;
            if (r_lo < M)
                g_support_h[(size_t)r_lo * (OUT_F / 2) + (col >> 1)] =
                    __floats2half2_rn(acc[mi][nj][0], acc[mi][nj][1]);
            if (r_hi < M)
                g_support_h[(size_t)r_hi * (OUT_F / 2) + (col >> 1)] =
                    __floats2half2_rn(acc[mi][nj][2], acc[mi][nj][3]);
        }
    }
}

// ===========================================================================
// Kernel 2: CSR row pointers from sorted edge_dst
// ===========================================================================
__global__ void build_row_start_kernel(const int* __restrict__ dst, int E, int N)
{
    int e = blockIdx.x * blockDim.x + threadIdx.x;
    if (e > E) return;
    if (e == 0) {
        int d1 = dst[0];
        for (int n = 0; n <= d1; n++) g_row_start[n] = 0;
    } else if (e == E) {
        int d0 = dst[E - 1];
        for (int n = d0 + 1; n <= N; n++) g_row_start[n] = E;
    } else {
        int d0 = dst[e - 1];
        int d1 = dst[e];
        for (int n = d0 + 1; n <= d1; n++) g_row_start[n] = e;
    }
}

// ===========================================================================
// Kernel 3: aggregation + bias + tanh.
// One warp per node; lane owns 4 cols (one 8-byte gather).
// src/val consumed via int4/float4 vector loads (after head alignment).
// ===========================================================================
__global__ __launch_bounds__(128)
void aggregate_kernel(const int*   __restrict__ src,
                      const float* __restrict__ val,
                      const float* __restrict__ bias,
                      float*       __restrict__ out,
                      int N)
{
    const int n = blockIdx.x * 4 + (threadIdx.x >> 5);
    if (n >= N) return;
    const int lane = threadIdx.x & 31;

    const uint2* __restrict__ sup = reinterpret_cast<const uint2*>(g_support_h);

    const int s = g_row_start[n];
    const int e = g_row_start[n + 1];

    float a0 = 0.f, a1 = 0.f, a2 = 0.f, a3 = 0.f;

    int i = s;
    // head: advance to 4-alignment for vector loads
    for (; i < e && (i & 3); i++) {
        float v = val[i];
        uint2 raw = sup[((uint32_t)src[i] << 5) + lane];
        float2 f0 = __half22float2(*reinterpret_cast<__half2*>(&raw.x));
        float2 f1 = __half22float2(*reinterpret_cast<__half2*>(&raw.y));
        a0 += v * f0.x; a1 += v * f0.y; a2 += v * f1.x; a3 += v * f1.y;
    }
    for (; i + 4 <= e; i += 4) {
        int4   s4 = *reinterpret_cast<const int4*>(src + i);
        float4 v4 = *reinterpret_cast<const float4*>(val + i);
        uint2 r0 = sup[((uint32_t)s4.x << 5) + lane];
        uint2 r1 = sup[((uint32_t)s4.y << 5) + lane];
        uint2 r2 = sup[((uint32_t)s4.z << 5) + lane];
        uint2 r3 = sup[((uint32_t)s4.w << 5) + lane];
        {
            float2 f0 = __half22float2(*reinterpret_cast<__half2*>(&r0.x));
            float2 f1 = __half22float2(*reinterpret_cast<__half2*>(&r0.y));
            a0 += v4.x * f0.x; a1 += v4.x * f0.y; a2 += v4.x * f1.x; a3 += v4.x * f1.y;
        }
        {
            float2 f0 = __half22float2(*reinterpret_cast<__half2*>(&r1.x));
            float2 f1 = __half22float2(*reinterpret_cast<__half2*>(&r1.y));
            a0 += v4.y * f0.x; a1 += v4.y * f0.y; a2 += v4.y * f1.x; a3 += v4.y * f1.y;
        }
        {
            float2 f0 = __half22float2(*reinterpret_cast<__half2*>(&r2.x));
            float2 f1 = __half22float2(*reinterpret_cast<__half2*>(&r2.y));
            a0 += v4.z * f0.x; a1 += v4.z * f0.y; a2 += v4.z * f1.x; a3 += v4.z * f1.y;
        }
        {
            float2 f0 = __half22float2(*reinterpret_cast<__half2*>(&r3.x));
            float2 f1 = __half22float2(*reinterpret_cast<__half2*>(&r3.y));
            a0 += v4.w * f0.x; a1 += v4.w * f0.y; a2 += v4.w * f1.x; a3 += v4.w * f1.y;
        }
    }
    for (; i < e; i++) {
        float v = val[i];
        uint2 raw = sup[((uint32_t)src[i] << 5) + lane];
        float2 f0 = __half22float2(*reinterpret_cast<__half2*>(&raw.x));
        float2 f1 = __half22float2(*reinterpret_cast<__half2*>(&raw.y));
        a0 += v * f0.x; a1 += v * f0.y; a2 += v * f1.x; a3 += v * f1.y;
    }

    float4 b = *reinterpret_cast<const float4*>(bias + lane * 4);
    *reinterpret_cast<float4*>(out + (size_t)n * OUT_F + lane * 4) =
        make_float4(tanhf(a0 + b.x), tanhf(a1 + b.y), tanhf(a2 + b.z), tanhf(a3 + b.w));
}

// ===========================================================================
// Launch
// ===========================================================================
extern "C" void kernel_launch(void* const* d_in, const int* in_sizes, int n_in,
                              void* d_out, int out_size)
{
    const float* x        = (const float*)d_in[0];
    const float* weight   = (const float*)d_in[1];
    const float* bias     = (const float*)d_in[2];
    const int*   edge_src = (const int*)  d_in[3];
    const int*   edge_dst = (const int*)  d_in[4];
    const float* edge_val = (const float*)d_in[5];
    float*       out      = (float*)d_out;

    const int M = in_sizes[0] / IN_F;   // 100000
    const int E = in_sizes[3];          // 1600000

    static bool attr_done = false;
    if (!attr_done) {
        cudaFuncSetAttribute(gemm_mma_kernel,
                             cudaFuncAttributeMaxDynamicSharedMemorySize, SM_TOTAL);
        attr_done = true;
    }

    // 0) W convert (fp32 -> fp16)
    convert_w_kernel<<<(IN_F * OUT_F + 255) / 256, 256>>>(weight);
    // 1) support = X @ W on tensor cores (fp16)
    gemm_mma_kernel<<<(M + 127) / 128, 256, SM_TOTAL>>>(x, M);
    // 2) CSR row pointers
    {
        int threads = 256;
        int blocks  = (E + 1 + threads - 1) / threads;
        build_row_start_kernel<<<blocks, threads>>>(edge_dst, E, M);
    }
    // 3) gather + segment-sum + bias + tanh (one warp per node)
    aggregate_kernel<<<(M + 3) / 4, 128>>>(edge_src, edge_val, bias, out, M);
}

// round 6
// speedup vs baseline: 3.2920x; 1.0171x over previous
#include <cuda_runtime.h>
#include <cuda_bf16.h>
#include <cuda_fp16.h>
#include <cstdint>

#define IN_F   256
#define OUT_F  128
#define NNODES 100000

// support = X @ W stored as fp16 (halves aggregate gather traffic)
__device__ __half2 g_support_h[(size_t)NNODES * (OUT_F / 2)];
__device__ int     g_row_start[NNODES + 1];
// Preconverted weight (fp16)
__device__ __half  g_wh[IN_F * OUT_F];

// ===========================================================================
// Helpers
// ===========================================================================
__device__ __forceinline__ uint32_t smem_u32(const void* p) {
    uint32_t a;
    asm("{ .reg .u64 t; cvta.to.shared.u64 t, %1; cvt.u32.u64 %0, t; }"
        : "=r"(a) : "l"(p));
    return a;
}
__device__ __forceinline__ void ldsm_x4(uint32_t* r, uint32_t addr) {
    asm volatile("ldmatrix.sync.aligned.m8n8.x4.shared.b16 {%0,%1,%2,%3}, [%4];"
                 : "=r"(r[0]), "=r"(r[1]), "=r"(r[2]), "=r"(r[3]) : "r"(addr));
}
__device__ __forceinline__ void ldsm_x4_t(uint32_t* r, uint32_t addr) {
    asm volatile("ldmatrix.sync.aligned.m8n8.x4.trans.shared.b16 {%0,%1,%2,%3}, [%4];"
                 : "=r"(r[0]), "=r"(r[1]), "=r"(r[2]), "=r"(r[3]) : "r"(addr));
}
__device__ __forceinline__ void mma_fp16(float* c, const uint32_t* a, const uint32_t* b) {
    asm volatile(
        "mma.sync.aligned.m16n8k16.row.col.f32.f16.f16.f32 "
        "{%0,%1,%2,%3}, {%4,%5,%6,%7}, {%8,%9}, {%0,%1,%2,%3};"
        : "+f"(c[0]), "+f"(c[1]), "+f"(c[2]), "+f"(c[3])
        : "r"(a[0]), "r"(a[1]), "r"(a[2]), "r"(a[3]), "r"(b[0]), "r"(b[1]));
}
__device__ __forceinline__ uint32_t packh2(float x, float y) {
    __half2 h = __floats2half2_rn(x, y);
    return *reinterpret_cast<uint32_t*>(&h);
}
// packed f32x2 ops (sm_100)
__device__ __forceinline__ uint64_t pack_f32x2(float lo, float hi) {
    uint64_t r;
    asm("mov.b64 %0, {%1, %2};" : "=l"(r) : "f"(lo), "f"(hi));
    return r;
}
__device__ __forceinline__ void fma_f32x2(uint64_t& d, uint64_t a, uint64_t b) {
    asm("fma.rn.f32x2 %0, %1, %2, %0;" : "+l"(d) : "l"(a), "l"(b));
}
__device__ __forceinline__ float2 unpack_f32x2(uint64_t v) {
    float lo, hi;
    asm("mov.b64 {%0, %1}, %2;" : "=f"(lo), "=f"(hi) : "l"(v));
    return make_float2(lo, hi);
}
// half2 word -> packed f32x2 (2 cvts + pack)
__device__ __forceinline__ uint64_t h2_to_f32x2(uint32_t h) {
    float2 f = __half22float2(*reinterpret_cast<__half2*>(&h));
    return pack_f32x2(f.x, f.y);
}

// ===========================================================================
// Kernel 0: prep — W fp32->fp16 convert + CSR row pointers (one launch)
// ===========================================================================
__global__ void prep_kernel(const float* __restrict__ W,
                            const int* __restrict__ dst, int E, int N)
{
    int gid = blockIdx.x * 256 + threadIdx.x;

    if (gid < IN_F * OUT_F)
        g_wh[gid] = __float2half_rn(W[gid]);

    int e = gid;
    if (e > E) return;
    if (e == 0) {
        int d1 = dst[0];
        for (int n = 0; n <= d1; n++) g_row_start[n] = 0;
    } else if (e == E) {
        int d0 = dst[E - 1];
        for (int n = d0 + 1; n <= N; n++) g_row_start[n] = E;
    } else {
        int d0 = dst[e - 1];
        int d1 = dst[e];
        for (int n = d0 + 1; n <= d1; n++) g_row_start[n] = e;
    }
}

// ===========================================================================
// Kernel 1: GEMM  support[M,128] = X[M,256] @ W[256,128], fp16 MMA.
// Block 128x128, 8 warps (2x4), warp tile 64x32, BK=32 fp32.
// Whole W resident in SMEM; A tiles double-buffered; 2 CTAs/SM.
// ===========================================================================
#define BKC 32
#define A_STRIDE 40
#define B_STRIDE 136
#define A_BUF_BYTES (128 * A_STRIDE * 2)
#define SM_A   0
#define SM_B   (2 * A_BUF_BYTES)
#define SM_TOTAL (SM_B + IN_F * B_STRIDE * 2)      // 90112

__global__ void __launch_bounds__(256, 2)
gemm_mma_kernel(const float* __restrict__ X, int M)
{
    extern __shared__ __align__(16) char smem[];
    const uint32_t sb = smem_u32(smem);

    const int tid    = threadIdx.x;
    const int lane   = tid & 31;
    const int wid    = tid >> 5;
    const int warp_m = (wid & 1) * 64;
    const int warp_n = (wid >> 1) * 32;
    const int row0   = blockIdx.x << 7;

    {
        const uint4* wp = reinterpret_cast<const uint4*>(g_wh);
        #pragma unroll
        for (int i = 0; i < 16; i++) {
            int e = tid + i * 256;
            int k = e >> 4, u = e & 15;
            uint4 h = wp[(size_t)k * 16 + u];
            uint32_t off = (uint32_t)(k * (B_STRIDE * 2) + u * 16);
            asm volatile("st.shared.v4.b32 [%0], {%1,%2,%3,%4};"
                         :: "r"(sb + SM_B + off), "r"(h.x), "r"(h.y), "r"(h.z), "r"(h.w) : "memory");
        }
    }

    float acc[4][4][4];
    #pragma unroll
    for (int i = 0; i < 4; i++)
        #pragma unroll
        for (int j = 0; j < 4; j++)
            #pragma unroll
            for (int q = 0; q < 4; q++) acc[i][j][q] = 0.f;

    const int a_r  = tid >> 3;
    const int a_kq = tid & 7;

    float4 xa[4];
    #pragma unroll
    for (int i = 0; i < 4; i++) {
        int gr = row0 + a_r + i * 32;
        xa[i] = (gr < M) ? *reinterpret_cast<const float4*>(X + (size_t)gr * IN_F + a_kq * 4)
                         : make_float4(0.f, 0.f, 0.f, 0.f);
    }
    #pragma unroll
    for (int i = 0; i < 4; i++) {
        int r = a_r + i * 32;
        uint32_t h0 = packh2(xa[i].x, xa[i].y), h1 = packh2(xa[i].z, xa[i].w);
        uint32_t off = (uint32_t)(r * (A_STRIDE * 2) + a_kq * 8);
        asm volatile("st.shared.v2.b32 [%0], {%1,%2};" :: "r"(sb + SM_A + off), "r"(h0), "r"(h1) : "memory");
    }
    __syncthreads();

    for (int c = 0; c < IN_F / BKC; c++) {
        const uint32_t abuf = sb + SM_A + (uint32_t)(c & 1) * A_BUF_BYTES;
        const bool more = (c + 1 < IN_F / BKC);

        if (more) {
            int k0n = (c + 1) * BKC;
            #pragma unroll
            for (int i = 0; i < 4; i++) {
                int gr = row0 + a_r + i * 32;
                xa[i] = (gr < M) ? *reinterpret_cast<const float4*>(X + (size_t)gr * IN_F + k0n + a_kq * 4)
                                 : make_float4(0.f, 0.f, 0.f, 0.f);
            }
        }

        #pragma unroll
        for (int ks = 0; ks < 2; ks++) {
            uint32_t ah[4][4], bh[2][4];
            const uint32_t a_col = (uint32_t)((ks * 16 + (lane >> 4) * 8) * 2);
            #pragma unroll
            for (int mi = 0; mi < 4; mi++) {
                uint32_t ar = (uint32_t)((warp_m + mi * 16 + (lane & 15)) * (A_STRIDE * 2)) + a_col;
                ldsm_x4(ah[mi], abuf + ar);
            }
            const uint32_t b_row =
                (uint32_t)((c * 32 + ks * 16 + (lane & 7) + ((lane >> 3) & 1) * 8) * (B_STRIDE * 2));
            #pragma unroll
            for (int nj = 0; nj < 2; nj++) {
                uint32_t br = b_row + (uint32_t)((warp_n + nj * 16 + (lane >> 4) * 8) * 2);
                ldsm_x4_t(bh[nj], sb + SM_B + br);
            }
            #pragma unroll
            for (int mi = 0; mi < 4; mi++) {
                #pragma unroll
                for (int nj = 0; nj < 4; nj++) {
                    uint32_t bf[2] = { bh[nj >> 1][(nj & 1) * 2], bh[nj >> 1][(nj & 1) * 2 + 1] };
                    mma_fp16(acc[mi][nj], ah[mi], bf);
                }
            }
        }

        if (more) {
            const uint32_t nbuf = sb + SM_A + (uint32_t)((c + 1) & 1) * A_BUF_BYTES;
            #pragma unroll
            for (int i = 0; i < 4; i++) {
                int r = a_r + i * 32;
                uint32_t h0 = packh2(xa[i].x, xa[i].y), h1 = packh2(xa[i].z, xa[i].w);
                uint32_t off = (uint32_t)(r * (A_STRIDE * 2) + a_kq * 8);
                asm volatile("st.shared.v2.b32 [%0], {%1,%2};" :: "r"(nbuf + off), "r"(h0), "r"(h1) : "memory");
            }
        }
        __syncthreads();
    }

    #pragma unroll
    for (int mi = 0; mi < 4; mi++) {
        int r_lo = row0 + warp_m + mi * 16 + (lane >> 2);
        int r_hi = r_lo + 8;
        #pragma unroll
        for (int nj = 0; nj < 4; nj++) {
            int col = warp_n + nj * 8 + (lane & 3) * 2;
            if (r_lo < M)
                g_support_h[(size_t)r_lo * (OUT_F / 2) + (col >> 1)] =
                    __floats2half2_rn(acc[mi][nj][0], acc[mi][nj][1]);
            if (r_hi < M)
                g_support_h[(size_t)r_hi * (OUT_F / 2) + (col >> 1)] =
                    __floats2half2_rn(acc[mi][nj][2], acc[mi][nj][3]);
        }
    }
}

// ===========================================================================
// Kernel 3: aggregation + bias + tanh.
// One warp per node; lane owns 4 cols (one 8-byte gather).
// Packed f32x2 FMA (FFMA2) halves FMA-pipe slots per edge.
// ===========================================================================
__global__ __launch_bounds__(128)
void aggregate_kernel(const int*   __restrict__ src,
                      const float* __restrict__ val,
                      const float* __restrict__ bias,
                      float*       __restrict__ out,
                      int N)
{
    const int n = blockIdx.x * 4 + (threadIdx.x >> 5);
    if (n >= N) return;
    const int lane = threadIdx.x & 31;

    const uint2* __restrict__ sup = reinterpret_cast<const uint2*>(g_support_h);

    const int s = g_row_start[n];
    const int e = g_row_start[n + 1];

    uint64_t acc01 = pack_f32x2(0.f, 0.f);
    uint64_t acc23 = pack_f32x2(0.f, 0.f);

    int i = s;
    for (; i < e && (i & 3); i++) {
        uint64_t vv = pack_f32x2(val[i], val[i]);
        uint2 raw = __ldg(sup + ((uint32_t)src[i] << 5) + lane);
        fma_f32x2(acc01, h2_to_f32x2(raw.x), vv);
        fma_f32x2(acc23, h2_to_f32x2(raw.y), vv);
    }
    for (; i + 4 <= e; i += 4) {
        int4   s4 = *reinterpret_cast<const int4*>(src + i);
        float4 v4 = *reinterpret_cast<const float4*>(val + i);
        uint2 r0 = __ldg(sup + ((uint32_t)s4.x << 5) + lane);
        uint2 r1 = __ldg(sup + ((uint32_t)s4.y << 5) + lane);
        uint2 r2 = __ldg(sup + ((uint32_t)s4.z << 5) + lane);
        uint2 r3 = __ldg(sup + ((uint32_t)s4.w << 5) + lane);
        uint64_t v0 = pack_f32x2(v4.x, v4.x);
        uint64_t v1 = pack_f32x2(v4.y, v4.y);
        uint64_t v2 = pack_f32x2(v4.z, v4.z);
        uint64_t v3 = pack_f32x2(v4.w, v4.w);
        fma_f32x2(acc01, h2_to_f32x2(r0.x), v0);
        fma_f32x2(acc23, h2_to_f32x2(r0.y), v0);
        fma_f32x2(acc01, h2_to_f32x2(r1.x), v1);
        fma_f32x2(acc23, h2_to_f32x2(r1.y), v1);
        fma_f32x2(acc01, h2_to_f32x2(r2.x), v2);
        fma_f32x2(acc23, h2_to_f32x2(r2.y), v2);
        fma_f32x2(acc01, h2_to_f32x2(r3.x), v3);
        fma_f32x2(acc23, h2_to_f32x2(r3.y), v3);
    }
    for (; i < e; i++) {
        uint64_t vv = pack_f32x2(val[i], val[i]);
        uint2 raw = __ldg(sup + ((uint32_t)src[i] << 5) + lane);
        fma_f32x2(acc01, h2_to_f32x2(raw.x), vv);
        fma_f32x2(acc23, h2_to_f32x2(raw.y), vv);
    }

    float2 a01 = unpack_f32x2(acc01);
    float2 a23 = unpack_f32x2(acc23);
    float4 b = *reinterpret_cast<const float4*>(bias + lane * 4);
    *reinterpret_cast<float4*>(out + (size_t)n * OUT_F + lane * 4) =
        make_float4(tanhf(a01.x + b.x), tanhf(a01.y + b.y),
                    tanhf(a23.x + b.z), tanhf(a23.y + b.w));
}

// ===========================================================================
// Launch
// ===========================================================================
extern "C" void kernel_launch(void* const* d_in, const int* in_sizes, int n_in,
                              void* d_out, int out_size)
{
    const float* x        = (const float*)d_in[0];
    const float* weight   = (const float*)d_in[1];
    const float* bias     = (const float*)d_in[2];
    const int*   edge_src = (const int*)  d_in[3];
    const int*   edge_dst = (const int*)  d_in[4];
    const float* edge_val = (const float*)d_in[5];
    float*       out      = (float*)d_out;

    const int M = in_sizes[0] / IN_F;   // 100000
    const int E = in_sizes[3];          // 1600000

    static bool attr_done = false;
    if (!attr_done) {
        cudaFuncSetAttribute(gemm_mma_kernel,
                             cudaFuncAttributeMaxDynamicSharedMemorySize, SM_TOTAL);
        attr_done = true;
    }

    // 0) prep: W fp16 convert + CSR row pointers (one launch)
    {
        int blocks = (E + 1 + 255) / 256;   // covers W part too (128 blocks)
        prep_kernel<<<blocks, 256>>>(weight, edge_dst, E, M);
    }
    // 1) support = X @ W on tensor cores (fp16)
    gemm_mma_kernel<<<(M + 127) / 128, 256, SM_TOTAL>>>(x, M);
    // 2) gather + segment-sum + bias + tanh (one warp per node)
    aggregate_kernel<<<(M + 3) / 4, 128>>>(edge_src, edge_val, bias, out, M);
}